// round 10
// baseline (speedup 1.0000x reference)
#include <cuda_runtime.h>
#include <cuda_bf16.h>
#include <cstdint>

// EMA over frames: y[n] = w*x[n] + (1-w)*y[n-1], y[-1] = initial_state.
// input (16,8,256,2048) f32, frames contiguous; init (16,8,256); weight (8,256).
// 32768 chains x 2048. One warp per chain.
//
// R10: measured-best R2 structure (8 elems/lane, 2-deep load pipeline,
// __ldcs input) with ONE change: output stores use __stwt (write-through,
// no L2 write-allocate) instead of __stcs. Tests whether removing L2
// dirty-victim writebacks from the write-once output stream improves
// DRAM bus-turnaround grouping. Everything else byte-identical.

#define N_FRAMES   2048
#define N_CHAINS   32768
#define CHAINS_PER_BATCH 2048
#define WARPS_PER_BLOCK 8
#define THREADS (WARPS_PER_BLOCK * 32)
#define ITERS (N_FRAMES / 256)         // 8

__global__ __launch_bounds__(THREADS)
void ema_scan_kernel(const float* __restrict__ x,
                     const float* __restrict__ init_state,
                     const float* __restrict__ weight,
                     float* __restrict__ y)
{
    const int warp = (blockIdx.x * WARPS_PER_BLOCK) + (threadIdx.x >> 5);
    const int lane = threadIdx.x & 31;

    float w = __ldg(&weight[warp & (CHAINS_PER_BATCH - 1)]);
    w = fminf(fmaxf(w, 0.0f), 1.0f);
    const float a = 1.0f - w;

    // exact binary powers of the decay
    const float a2   = a    * a;
    const float a3   = a2   * a;
    const float a4   = a2   * a2;
    const float a5   = a4   * a;
    const float a6   = a4   * a2;
    const float a7   = a4   * a3;
    const float a8   = a4   * a4;
    const float a16  = a8   * a8;
    const float a32  = a16  * a16;
    const float a64  = a32  * a32;
    const float a128 = a64  * a64;

    // pw = a^(8*lane) from lane bits (exact products)
    float pw = 1.0f;
    if (lane & 1)  pw *= a8;
    if (lane & 2)  pw *= a16;
    if (lane & 4)  pw *= a32;
    if (lane & 8)  pw *= a64;
    if (lane & 16) pw *= a128;

    const float4* __restrict__ xin =
        reinterpret_cast<const float4*>(x + (size_t)warp * N_FRAMES);
    float4* __restrict__ yout =
        reinterpret_cast<float4*>(y + (size_t)warp * N_FRAMES);

    float carry = __ldg(&init_state[warp]);

    // lane's two float4s are consecutive: float4 index = it*64 + lane*2 (+1)
    const int li = lane * 2;

    // prime the pipeline
    float4 c0 = __ldcs(&xin[li]);
    float4 c1 = __ldcs(&xin[li + 1]);

    #pragma unroll
    for (int it = 0; it < ITERS; ++it) {
        float4 n0, n1;
        if (it + 1 < ITERS) {
            n0 = __ldcs(&xin[(it + 1) * 64 + li]);
            n1 = __ldcs(&xin[(it + 1) * 64 + li + 1]);
        }

        // local 8-step scan, zero-seeded: s_j = a*s_{j-1} + w*x_j
        float s0 = w * c0.x;
        float s1 = fmaf(a, s0, w * c0.y);
        float s2 = fmaf(a, s1, w * c0.z);
        float s3 = fmaf(a, s2, w * c0.w);
        float s4 = fmaf(a, s3, w * c1.x);
        float s5 = fmaf(a, s4, w * c1.y);
        float s6 = fmaf(a, s5, w * c1.z);
        float s7 = fmaf(a, s6, w * c1.w);

        // warp Kogge-Stone over lane carries, segment factor a^8
        float t = s7;
        float f = a8;
        #pragma unroll
        for (int off = 1; off < 32; off <<= 1) {
            float up = __shfl_up_sync(0xffffffffu, t, off);
            if (lane >= off) t = fmaf(f, up, t);
            f = f * f;   // a8 -> a16 -> a32 -> a64 -> a128
        }

        // exclusive prefix from preceding lanes + scaled chain carry
        float excl = __shfl_up_sync(0xffffffffu, t, 1);
        if (lane == 0) excl = 0.0f;
        const float pre = fmaf(pw, carry, excl);

        float4 o0, o1;
        o0.x = fmaf(a,  pre, s0);
        o0.y = fmaf(a2, pre, s1);
        o0.z = fmaf(a3, pre, s2);
        o0.w = fmaf(a4, pre, s3);
        o1.x = fmaf(a5, pre, s4);
        o1.y = fmaf(a6, pre, s5);
        o1.z = fmaf(a7, pre, s6);
        o1.w = fmaf(a8, pre, s7);

        __stwt(&yout[it * 64 + li],     o0);
        __stwt(&yout[it * 64 + li + 1], o1);

        carry = __shfl_sync(0xffffffffu, o1.w, 31);

        c0 = n0;
        c1 = n1;
    }
}

extern "C" void kernel_launch(void* const* d_in, const int* in_sizes, int n_in,
                              void* d_out, int out_size)
{
    const float* x    = (const float*)d_in[0];
    const float* init = (const float*)d_in[1];
    const float* wgt  = (const float*)d_in[2];
    float* y          = (float*)d_out;

    const int blocks = N_CHAINS / WARPS_PER_BLOCK;   // 4096
    ema_scan_kernel<<<blocks, THREADS>>>(x, init, wgt, y);
}

// round 11
// speedup vs baseline: 1.0193x; 1.0193x over previous
#include <cuda_runtime.h>
#include <cuda_bf16.h>
#include <cstdint>

// EMA over frames: y[n] = w*x[n] + (1-w)*y[n-1], y[-1] = initial_state.
// input (16,8,256,2048) f32, frames contiguous; init (16,8,256); weight (8,256).
// 32768 chains x 2048. One warp per chain.
//
// FINAL. Measured optimum across 9 structural/policy variants:
//   - 8 contiguous elements per lane (256-element chunks, 8 iters);
//     lane*2 float4 layout keeps every LDG.128/STG.128 on 8 fully-consumed
//     128B lines (16/lane broke per-instruction coalescing: -9pts DRAM).
//   - 2-deep software load pipeline.
//   - __ldcs input (read-once) / __stcs output (write-once).
//   - 4096-block launch (persistent grid blew registers; launch-bounds cap
//     degraded scheduling; __stwt neutral).
// Converged at 6.2 TB/s = ~78-79% of HBM spec -- the mixed 1:1 read/write
// stream ceiling on this part. kernel ~77.3us, rel_err ~3e-7.

#define N_FRAMES   2048
#define N_CHAINS   32768
#define CHAINS_PER_BATCH 2048
#define WARPS_PER_BLOCK 8
#define THREADS (WARPS_PER_BLOCK * 32)
#define ITERS (N_FRAMES / 256)         // 8

__global__ __launch_bounds__(THREADS)
void ema_scan_kernel(const float* __restrict__ x,
                     const float* __restrict__ init_state,
                     const float* __restrict__ weight,
                     float* __restrict__ y)
{
    const int warp = (blockIdx.x * WARPS_PER_BLOCK) + (threadIdx.x >> 5);
    const int lane = threadIdx.x & 31;

    float w = __ldg(&weight[warp & (CHAINS_PER_BATCH - 1)]);
    w = fminf(fmaxf(w, 0.0f), 1.0f);
    const float a = 1.0f - w;

    // exact binary powers of the decay
    const float a2   = a    * a;
    const float a3   = a2   * a;
    const float a4   = a2   * a2;
    const float a5   = a4   * a;
    const float a6   = a4   * a2;
    const float a7   = a4   * a3;
    const float a8   = a4   * a4;
    const float a16  = a8   * a8;
    const float a32  = a16  * a16;
    const float a64  = a32  * a32;
    const float a128 = a64  * a64;

    // pw = a^(8*lane) from lane bits (exact products)
    float pw = 1.0f;
    if (lane & 1)  pw *= a8;
    if (lane & 2)  pw *= a16;
    if (lane & 4)  pw *= a32;
    if (lane & 8)  pw *= a64;
    if (lane & 16) pw *= a128;

    const float4* __restrict__ xin =
        reinterpret_cast<const float4*>(x + (size_t)warp * N_FRAMES);
    float4* __restrict__ yout =
        reinterpret_cast<float4*>(y + (size_t)warp * N_FRAMES);

    float carry = __ldg(&init_state[warp]);

    // lane's two float4s are consecutive: float4 index = it*64 + lane*2 (+1)
    const int li = lane * 2;

    // prime the pipeline
    float4 c0 = __ldcs(&xin[li]);
    float4 c1 = __ldcs(&xin[li + 1]);

    #pragma unroll
    for (int it = 0; it < ITERS; ++it) {
        float4 n0, n1;
        if (it + 1 < ITERS) {
            n0 = __ldcs(&xin[(it + 1) * 64 + li]);
            n1 = __ldcs(&xin[(it + 1) * 64 + li + 1]);
        }

        // local 8-step scan, zero-seeded: s_j = a*s_{j-1} + w*x_j
        float s0 = w * c0.x;
        float s1 = fmaf(a, s0, w * c0.y);
        float s2 = fmaf(a, s1, w * c0.z);
        float s3 = fmaf(a, s2, w * c0.w);
        float s4 = fmaf(a, s3, w * c1.x);
        float s5 = fmaf(a, s4, w * c1.y);
        float s6 = fmaf(a, s5, w * c1.z);
        float s7 = fmaf(a, s6, w * c1.w);

        // warp Kogge-Stone over lane carries, segment factor a^8
        float t = s7;
        float f = a8;
        #pragma unroll
        for (int off = 1; off < 32; off <<= 1) {
            float up = __shfl_up_sync(0xffffffffu, t, off);
            if (lane >= off) t = fmaf(f, up, t);
            f = f * f;   // a8 -> a16 -> a32 -> a64 -> a128
        }

        // exclusive prefix from preceding lanes + scaled chain carry
        float excl = __shfl_up_sync(0xffffffffu, t, 1);
        if (lane == 0) excl = 0.0f;
        const float pre = fmaf(pw, carry, excl);

        float4 o0, o1;
        o0.x = fmaf(a,  pre, s0);
        o0.y = fmaf(a2, pre, s1);
        o0.z = fmaf(a3, pre, s2);
        o0.w = fmaf(a4, pre, s3);
        o1.x = fmaf(a5, pre, s4);
        o1.y = fmaf(a6, pre, s5);
        o1.z = fmaf(a7, pre, s6);
        o1.w = fmaf(a8, pre, s7);

        __stcs(&yout[it * 64 + li],     o0);
        __stcs(&yout[it * 64 + li + 1], o1);

        carry = __shfl_sync(0xffffffffu, o1.w, 31);

        c0 = n0;
        c1 = n1;
    }
}

extern "C" void kernel_launch(void* const* d_in, const int* in_sizes, int n_in,
                              void* d_out, int out_size)
{
    const float* x    = (const float*)d_in[0];
    const float* init = (const float*)d_in[1];
    const float* wgt  = (const float*)d_in[2];
    float* y          = (float*)d_out;

    const int blocks = N_CHAINS / WARPS_PER_BLOCK;   // 4096
    ema_scan_kernel<<<blocks, THREADS>>>(x, init, wgt, y);
}

// round 12
// speedup vs baseline: 1.0208x; 1.0015x over previous
#include <cuda_runtime.h>
#include <cuda_bf16.h>
#include <cstdint>

// EMA over frames: y[n] = w*x[n] + (1-w)*y[n-1], y[-1] = initial_state.
// input (16,8,256,2048) f32, frames contiguous; init (16,8,256); weight (8,256).
// 32768 chains x 2048. One warp per chain.
//
// R12: identical per-warp code to the measured optimum (R2/R11: 8 elems/lane,
// 2-deep load pipeline, __ldcs/__stcs), single variable changed:
// block = 128 threads (4 warps), grid = 8192 CTAs. Tests whether finer CTA
// scheduling granularity improves wave packing / L2-die balance. Occupancy
// limiter (regs=48) is unchanged.

#define N_FRAMES   2048
#define N_CHAINS   32768
#define CHAINS_PER_BATCH 2048
#define WARPS_PER_BLOCK 4
#define THREADS (WARPS_PER_BLOCK * 32)
#define ITERS (N_FRAMES / 256)         // 8

__global__ __launch_bounds__(THREADS)
void ema_scan_kernel(const float* __restrict__ x,
                     const float* __restrict__ init_state,
                     const float* __restrict__ weight,
                     float* __restrict__ y)
{
    const int warp = (blockIdx.x * WARPS_PER_BLOCK) + (threadIdx.x >> 5);
    const int lane = threadIdx.x & 31;

    float w = __ldg(&weight[warp & (CHAINS_PER_BATCH - 1)]);
    w = fminf(fmaxf(w, 0.0f), 1.0f);
    const float a = 1.0f - w;

    // exact binary powers of the decay
    const float a2   = a    * a;
    const float a3   = a2   * a;
    const float a4   = a2   * a2;
    const float a5   = a4   * a;
    const float a6   = a4   * a2;
    const float a7   = a4   * a3;
    const float a8   = a4   * a4;
    const float a16  = a8   * a8;
    const float a32  = a16  * a16;
    const float a64  = a32  * a32;
    const float a128 = a64  * a64;

    // pw = a^(8*lane) from lane bits (exact products)
    float pw = 1.0f;
    if (lane & 1)  pw *= a8;
    if (lane & 2)  pw *= a16;
    if (lane & 4)  pw *= a32;
    if (lane & 8)  pw *= a64;
    if (lane & 16) pw *= a128;

    const float4* __restrict__ xin =
        reinterpret_cast<const float4*>(x + (size_t)warp * N_FRAMES);
    float4* __restrict__ yout =
        reinterpret_cast<float4*>(y + (size_t)warp * N_FRAMES);

    float carry = __ldg(&init_state[warp]);

    // lane's two float4s are consecutive: float4 index = it*64 + lane*2 (+1)
    const int li = lane * 2;

    // prime the pipeline
    float4 c0 = __ldcs(&xin[li]);
    float4 c1 = __ldcs(&xin[li + 1]);

    #pragma unroll
    for (int it = 0; it < ITERS; ++it) {
        float4 n0, n1;
        if (it + 1 < ITERS) {
            n0 = __ldcs(&xin[(it + 1) * 64 + li]);
            n1 = __ldcs(&xin[(it + 1) * 64 + li + 1]);
        }

        // local 8-step scan, zero-seeded: s_j = a*s_{j-1} + w*x_j
        float s0 = w * c0.x;
        float s1 = fmaf(a, s0, w * c0.y);
        float s2 = fmaf(a, s1, w * c0.z);
        float s3 = fmaf(a, s2, w * c0.w);
        float s4 = fmaf(a, s3, w * c1.x);
        float s5 = fmaf(a, s4, w * c1.y);
        float s6 = fmaf(a, s5, w * c1.z);
        float s7 = fmaf(a, s6, w * c1.w);

        // warp Kogge-Stone over lane carries, segment factor a^8
        float t = s7;
        float f = a8;
        #pragma unroll
        for (int off = 1; off < 32; off <<= 1) {
            float up = __shfl_up_sync(0xffffffffu, t, off);
            if (lane >= off) t = fmaf(f, up, t);
            f = f * f;   // a8 -> a16 -> a32 -> a64 -> a128
        }

        // exclusive prefix from preceding lanes + scaled chain carry
        float excl = __shfl_up_sync(0xffffffffu, t, 1);
        if (lane == 0) excl = 0.0f;
        const float pre = fmaf(pw, carry, excl);

        float4 o0, o1;
        o0.x = fmaf(a,  pre, s0);
        o0.y = fmaf(a2, pre, s1);
        o0.z = fmaf(a3, pre, s2);
        o0.w = fmaf(a4, pre, s3);
        o1.x = fmaf(a5, pre, s4);
        o1.y = fmaf(a6, pre, s5);
        o1.z = fmaf(a7, pre, s6);
        o1.w = fmaf(a8, pre, s7);

        __stcs(&yout[it * 64 + li],     o0);
        __stcs(&yout[it * 64 + li + 1], o1);

        carry = __shfl_sync(0xffffffffu, o1.w, 31);

        c0 = n0;
        c1 = n1;
    }
}

extern "C" void kernel_launch(void* const* d_in, const int* in_sizes, int n_in,
                              void* d_out, int out_size)
{
    const float* x    = (const float*)d_in[0];
    const float* init = (const float*)d_in[1];
    const float* wgt  = (const float*)d_in[2];
    float* y          = (float*)d_out;

    const int blocks = N_CHAINS / WARPS_PER_BLOCK;   // 8192
    ema_scan_kernel<<<blocks, THREADS>>>(x, init, wgt, y);
}